// round 1
// baseline (speedup 1.0000x reference)
#include <cuda_runtime.h>

// Problem constants (fixed shapes from setup_inputs)
#define NS      51          // hidden size
#define NG      204         // 4*NS gates
#define T_LEN   2048
#define B_TOT   8192
#define ROWS    64          // batch rows per block
#define SLICES  4
#define RPS     (ROWS / SLICES)   // 16 rows per slice
#define RINNER  4
#define NTHREADS (NS * SLICES)    // 204
#define WPITCH  208         // pitch for k-major weight tiles
#define HPITCH  53          // pitch for h state (coprime with 32 -> conflict-free)

__device__ __forceinline__ float sigm(float v) {
    return 1.0f / (1.0f + __expf(-v));
}
__device__ __forceinline__ float tanh_fast(float v) {
    // 2*sigmoid(2v) - 1 ; accurate to ~1e-6 rel via __expf
    return 2.0f / (1.0f + __expf(-2.0f * v)) - 1.0f;
}

__global__ __launch_bounds__(NTHREADS, 1)
void lstm2_persistent_kernel(
    const float* __restrict__ x,      // [B, T, 1]
    const float* __restrict__ Wih1,   // [204, 1]
    const float* __restrict__ Whh1,   // [204, 51]
    const float* __restrict__ bih1,   // [204]
    const float* __restrict__ bhh1,   // [204]
    const float* __restrict__ Wih2,   // [204, 51]
    const float* __restrict__ Whh2,   // [204, 51]
    const float* __restrict__ bih2,   // [204]
    const float* __restrict__ bhh2,   // [204]
    const float* __restrict__ Wlin,   // [1, 51]
    const float* __restrict__ blin,   // [1]
    float* __restrict__ out)          // [B, T]
{
    extern __shared__ float sm[];
    float* wh1 = sm;                         // [NS][WPITCH] k-major: wh1[k*WPITCH+g] = Whh1[g][k]
    float* wi2 = wh1 + NS * WPITCH;
    float* wh2 = wi2 + NS * WPITCH;
    float* h1  = wh2 + NS * WPITCH;          // [ROWS][HPITCH]
    float* h2  = h1 + ROWS * HPITCH;
    float* b1  = h2 + ROWS * HPITCH;         // [NG] combined bias
    float* b2  = b1 + NG;
    float* wi1 = b2 + NG;                    // [NG]
    float* wl  = wi1 + NG;                   // [NS]
    float* xs  = wl + NS;                    // [ROWS]

    const int tid = threadIdx.x;
    const int rb  = blockIdx.x * ROWS;

    // ---- init: stage weights (transposed), biases, states ----
    for (int i = tid; i < NG * NS; i += NTHREADS) {
        int g = i / NS, k = i % NS;
        wh1[k * WPITCH + g] = Whh1[i];
        wi2[k * WPITCH + g] = Wih2[i];
        wh2[k * WPITCH + g] = Whh2[i];
    }
    for (int i = tid; i < NG; i += NTHREADS) {
        b1[i]  = bih1[i] + bhh1[i];
        b2[i]  = bih2[i] + bhh2[i];
        wi1[i] = Wih1[i];
    }
    for (int i = tid; i < NS; i += NTHREADS) wl[i] = Wlin[i];
    for (int i = tid; i < ROWS * HPITCH; i += NTHREADS) { h1[i] = 0.0f; h2[i] = 0.0f; }
    if (tid < ROWS) xs[tid] = x[(size_t)(rb + tid) * T_LEN];
    const float blin_v = blin[0];
    __syncthreads();

    const int j  = tid % NS;          // gate column 0..50
    const int sl = tid / NS;          // row slice 0..3
    const int r0 = sl * RPS;          // first row (local) of this slice

    float c1r[RPS], c2r[RPS], h1n[RPS], h2n[RPS];
    #pragma unroll
    for (int i = 0; i < RPS; ++i) { c1r[i] = 0.0f; c2r[i] = 0.0f; }

    const float bi1_0 = b1[j],        bi1_1 = b1[j + NS];
    const float bi1_2 = b1[j + 2*NS], bi1_3 = b1[j + 3*NS];
    const float bi2_0 = b2[j],        bi2_1 = b2[j + NS];
    const float bi2_2 = b2[j + 2*NS], bi2_3 = b2[j + 3*NS];
    const float wx0 = wi1[j],        wx1 = wi1[j + NS];
    const float wx2 = wi1[j + 2*NS], wx3 = wi1[j + 3*NS];

    for (int t = 0; t < T_LEN; ++t) {
        // ---------- Phase A: layer-1 gates + pointwise (reads h1 old) ----------
        for (int rg = 0; rg < RPS; rg += RINNER) {
            float a0[RINNER], a1[RINNER], a2[RINNER], a3[RINNER];
            #pragma unroll
            for (int rr = 0; rr < RINNER; ++rr) {
                float xv = xs[r0 + rg + rr];
                a0[rr] = fmaf(xv, wx0, bi1_0);
                a1[rr] = fmaf(xv, wx1, bi1_1);
                a2[rr] = fmaf(xv, wx2, bi1_2);
                a3[rr] = fmaf(xv, wx3, bi1_3);
            }
            for (int k = 0; k < NS; ++k) {
                const float* wrow = wh1 + k * WPITCH;
                float w0 = wrow[j], w1 = wrow[j + NS];
                float w2 = wrow[j + 2*NS], w3 = wrow[j + 3*NS];
                #pragma unroll
                for (int rr = 0; rr < RINNER; ++rr) {
                    float hv = h1[(r0 + rg + rr) * HPITCH + k];
                    a0[rr] = fmaf(hv, w0, a0[rr]);
                    a1[rr] = fmaf(hv, w1, a1[rr]);
                    a2[rr] = fmaf(hv, w2, a2[rr]);
                    a3[rr] = fmaf(hv, w3, a3[rr]);
                }
            }
            #pragma unroll
            for (int rr = 0; rr < RINNER; ++rr) {
                int ri = rg + rr;
                float ig = sigm(a0[rr]);
                float fg = sigm(a1[rr]);
                float gg = tanh_fast(a2[rr]);
                float og = sigm(a3[rr]);
                float c  = fmaf(fg, c1r[ri], ig * gg);
                c1r[ri] = c;
                h1n[ri] = og * tanh_fast(c);
            }
        }
        __syncthreads();   // everyone done reading h1(old)

        // ---------- Phase B: publish h1 new ----------
        #pragma unroll
        for (int ri = 0; ri < RPS; ++ri) h1[(r0 + ri) * HPITCH + j] = h1n[ri];
        __syncthreads();   // h1(new) visible

        // ---------- Phase C: layer-2 gates + pointwise (reads h1 new, h2 old) ----------
        for (int rg = 0; rg < RPS; rg += RINNER) {
            float a0[RINNER], a1[RINNER], a2[RINNER], a3[RINNER];
            #pragma unroll
            for (int rr = 0; rr < RINNER; ++rr) {
                a0[rr] = bi2_0; a1[rr] = bi2_1; a2[rr] = bi2_2; a3[rr] = bi2_3;
            }
            for (int k = 0; k < NS; ++k) {
                const float* wrowi = wi2 + k * WPITCH;
                const float* wrowh = wh2 + k * WPITCH;
                float wi_0 = wrowi[j], wi_1 = wrowi[j + NS];
                float wi_2 = wrowi[j + 2*NS], wi_3 = wrowi[j + 3*NS];
                float whh0 = wrowh[j], whh1v = wrowh[j + NS];
                float whh2v = wrowh[j + 2*NS], whh3 = wrowh[j + 3*NS];
                #pragma unroll
                for (int rr = 0; rr < RINNER; ++rr) {
                    int ro = (r0 + rg + rr) * HPITCH + k;
                    float hv1 = h1[ro];
                    float hv2 = h2[ro];
                    a0[rr] = fmaf(hv1, wi_0, a0[rr]);
                    a1[rr] = fmaf(hv1, wi_1, a1[rr]);
                    a2[rr] = fmaf(hv1, wi_2, a2[rr]);
                    a3[rr] = fmaf(hv1, wi_3, a3[rr]);
                    a0[rr] = fmaf(hv2, whh0,  a0[rr]);
                    a1[rr] = fmaf(hv2, whh1v, a1[rr]);
                    a2[rr] = fmaf(hv2, whh2v, a2[rr]);
                    a3[rr] = fmaf(hv2, whh3,  a3[rr]);
                }
            }
            #pragma unroll
            for (int rr = 0; rr < RINNER; ++rr) {
                int ri = rg + rr;
                float ig = sigm(a0[rr]);
                float fg = sigm(a1[rr]);
                float gg = tanh_fast(a2[rr]);
                float og = sigm(a3[rr]);
                float c  = fmaf(fg, c2r[ri], ig * gg);
                c2r[ri] = c;
                h2n[ri] = og * tanh_fast(c);
            }
        }
        __syncthreads();   // everyone done reading h2(old)

        // ---------- Phase D: publish h2 new ----------
        #pragma unroll
        for (int ri = 0; ri < RPS; ++ri) h2[(r0 + ri) * HPITCH + j] = h2n[ri];
        __syncthreads();   // h2(new) visible

        // ---------- Phase E: output projection + prefetch next x ----------
        if (tid < ROWS) {
            float acc = blin_v;
            #pragma unroll
            for (int k = 0; k < NS; ++k)
                acc = fmaf(h2[tid * HPITCH + k], wl[k], acc);
            out[(size_t)(rb + tid) * T_LEN + t] = acc;
        } else if (tid < 2 * ROWS) {
            int r = tid - ROWS;
            if (t + 1 < T_LEN)
                xs[r] = x[(size_t)(rb + r) * T_LEN + (t + 1)];
        }
        __syncthreads();   // xs ready; h2 reads done before next write
    }
}

extern "C" void kernel_launch(void* const* d_in, const int* in_sizes, int n_in,
                              void* d_out, int out_size) {
    const float* x    = (const float*)d_in[0];
    const float* Wih1 = (const float*)d_in[1];
    const float* Whh1 = (const float*)d_in[2];
    const float* bih1 = (const float*)d_in[3];
    const float* bhh1 = (const float*)d_in[4];
    const float* Wih2 = (const float*)d_in[5];
    const float* Whh2 = (const float*)d_in[6];
    const float* bih2 = (const float*)d_in[7];
    const float* bhh2 = (const float*)d_in[8];
    const float* Wlin = (const float*)d_in[9];
    const float* blin = (const float*)d_in[10];
    float* out = (float*)d_out;

    // Dynamic SMEM: 3 weight tiles + 2 state arrays + biases/vecs
    size_t smem = (size_t)(3 * NS * WPITCH + 2 * ROWS * HPITCH + 3 * NG + NS + ROWS)
                  * sizeof(float);
    cudaFuncSetAttribute(lstm2_persistent_kernel,
                         cudaFuncAttributeMaxDynamicSharedMemorySize, (int)smem);

    dim3 grid(B_TOT / ROWS);      // 128 blocks
    dim3 block(NTHREADS);         // 204 threads
    lstm2_persistent_kernel<<<grid, block, smem>>>(
        x, Wih1, Whh1, bih1, bhh1, Wih2, Whh2, bih2, bhh2, Wlin, blin, out);
}

// round 2
// speedup vs baseline: 1.8154x; 1.8154x over previous
#include <cuda_runtime.h>

// Problem constants (fixed shapes)
#define NS      51                // hidden size
#define NG      204               // 4*NS
#define T_LEN   2048
#define B_TOT   8192
#define ROWS    64                // batch rows per block
#define SLICES  8
#define RPS     (ROWS / SLICES)   // 8 rows per thread
#define NTHREADS (NS * SLICES)    // 408
#define HP      68                // floats per k-row of h (68%4==0, pad kills bank conflicts)
#define HSZ     (NS * HP)         // one h buffer
#define WQP     52                // float4 pitch per k-row of weight quads

typedef unsigned long long ull;

__device__ __forceinline__ ull pack2(float lo, float hi) {
    ull r; asm("mov.b64 %0, {%1, %2};" : "=l"(r) : "f"(lo), "f"(hi)); return r;
}
__device__ __forceinline__ ull fma2(ull a, ull b, ull c) {
    ull d; asm("fma.rn.f32x2 %0, %1, %2, %3;" : "=l"(d) : "l"(a), "l"(b), "l"(c)); return d;
}
__device__ __forceinline__ float2 unpack2(ull v) {
    float lo, hi; asm("mov.b64 {%0, %1}, %2;" : "=f"(lo), "=f"(hi) : "l"(v));
    return make_float2(lo, hi);
}
__device__ __forceinline__ float sigm(float v) {
    return 1.0f / (1.0f + __expf(-v));
}
__device__ __forceinline__ float tanh_fast(float v) {
    return 2.0f / (1.0f + __expf(-2.0f * v)) - 1.0f;
}

// One packed activation step for 2 rows: gates (i,f,g,o), updates c[0..1], writes hn[0..1]
__device__ __forceinline__ void lstm_act2(ull A0, ull A1, ull A2, ull A3,
                                          float* c, float* hn) {
    float2 ai = unpack2(A0), af = unpack2(A1), ag = unpack2(A2), ao = unpack2(A3);
    float cx = fmaf(sigm(af.x), c[0], sigm(ai.x) * tanh_fast(ag.x));
    c[0] = cx;  hn[0] = sigm(ao.x) * tanh_fast(cx);
    float cy = fmaf(sigm(af.y), c[1], sigm(ai.y) * tanh_fast(ag.y));
    c[1] = cy;  hn[1] = sigm(ao.y) * tanh_fast(cy);
}

__global__ __launch_bounds__(NTHREADS, 1)
void lstm2_f32x2_kernel(
    const float* __restrict__ x,      // [B, T]
    const float* __restrict__ Wih1,   // [204, 1]
    const float* __restrict__ Whh1,   // [204, 51]
    const float* __restrict__ bih1,
    const float* __restrict__ bhh1,
    const float* __restrict__ Wih2,   // [204, 51]
    const float* __restrict__ Whh2,   // [204, 51]
    const float* __restrict__ bih2,
    const float* __restrict__ bhh2,
    const float* __restrict__ Wlin,   // [1, 51]
    const float* __restrict__ blin,
    float* __restrict__ out)          // [B, T]
{
    extern __shared__ float sm[];
    // weight quads: wq[k*WQP + j] = float4(W[i-gate j][k], W[f..], W[g..], W[o..])
    float4* wq1  = (float4*)sm;                       // Whh1
    float4* wqi2 = wq1  + NS * WQP;
    float4* wqh2 = wqi2 + NS * WQP;
    float*  h1   = (float*)(wqh2 + NS * WQP);         // [2][NS][HP] double-buffered
    float*  h2   = h1 + 2 * HSZ;
    float*  b1s  = h2 + 2 * HSZ;                      // [NG] combined biases
    float*  b2s  = b1s + NG;
    float*  wi1s = b2s + NG;                          // [NG]
    float*  wls  = wi1s + NG;                         // [52]
    float*  xs   = wls + 52;                          // [ROWS]

    const int tid = threadIdx.x;
    const int rb  = blockIdx.x * ROWS;

    // ---- init: transpose weights into gate-quads, combine biases, zero states ----
    for (int i = tid; i < NG * NS; i += NTHREADS) {
        int g = i / NS, k = i % NS;
        int j = g % NS, gi = g / NS;
        ((float*)&wq1 [k * WQP + j])[gi] = Whh1[i];
        ((float*)&wqi2[k * WQP + j])[gi] = Wih2[i];
        ((float*)&wqh2[k * WQP + j])[gi] = Whh2[i];
    }
    for (int i = tid; i < NG; i += NTHREADS) {
        b1s[i]  = bih1[i] + bhh1[i];
        b2s[i]  = bih2[i] + bhh2[i];
        wi1s[i] = Wih1[i];
    }
    for (int i = tid; i < NS; i += NTHREADS) wls[i] = Wlin[i];
    for (int i = tid; i < 2 * HSZ; i += NTHREADS) { h1[i] = 0.0f; h2[i] = 0.0f; }
    if (tid < ROWS) xs[tid] = x[(size_t)(rb + tid) * T_LEN];
    const float blin_v = blin[0];
    __syncthreads();

    const int j  = tid % NS;          // hidden-unit / gate column 0..50
    const int sl = tid / NS;          // row slice 0..7
    const int r0 = sl * RPS;          // first local row of this slice

    // per-thread packed constants
    ull wxd[4], b1d[4], b2d[4];
    #pragma unroll
    for (int gi = 0; gi < 4; ++gi) {
        float wv = wi1s[j + gi * NS];
        wxd[gi] = pack2(wv, wv);
        float bv1 = b1s[j + gi * NS]; b1d[gi] = pack2(bv1, bv1);
        float bv2 = b2s[j + gi * NS]; b2d[gi] = pack2(bv2, bv2);
    }

    float c1[RPS], c2[RPS];
    #pragma unroll
    for (int i = 0; i < RPS; ++i) { c1[i] = 0.0f; c2[i] = 0.0f; }

    int bf = 0;
    for (int t = 0; t < T_LEN; ++t) {
        const int nb = bf ^ 1;
        const float* h1o = h1 + bf * HSZ;
        float*       h1n = h1 + nb * HSZ;
        const float* h2o = h2 + bf * HSZ;
        float*       h2n = h2 + nb * HSZ;

        // ================= Layer 1: gates + pointwise, write h1(new) =================
        {
            ull a0[4], a1[4], a2[4], a3[4];
            ulonglong2 xA = *(const ulonglong2*)(xs + r0);
            ulonglong2 xB = *(const ulonglong2*)(xs + r0 + 4);
            ull xp[4] = {xA.x, xA.y, xB.x, xB.y};
            #pragma unroll
            for (int p = 0; p < 4; ++p) {
                a0[p] = fma2(xp[p], wxd[0], b1d[0]);
                a1[p] = fma2(xp[p], wxd[1], b1d[1]);
                a2[p] = fma2(xp[p], wxd[2], b1d[2]);
                a3[p] = fma2(xp[p], wxd[3], b1d[3]);
            }
            #pragma unroll 3
            for (int k = 0; k < NS; ++k) {
                float4 w = wq1[k * WQP + j];
                ull w0 = pack2(w.x, w.x), w1 = pack2(w.y, w.y);
                ull w2 = pack2(w.z, w.z), w3 = pack2(w.w, w.w);
                const float* hp = h1o + k * HP + r0;
                ulonglong2 hA = *(const ulonglong2*)hp;
                ulonglong2 hB = *(const ulonglong2*)(hp + 4);
                ull hv[4] = {hA.x, hA.y, hB.x, hB.y};
                #pragma unroll
                for (int p = 0; p < 4; ++p) {
                    a0[p] = fma2(hv[p], w0, a0[p]);
                    a1[p] = fma2(hv[p], w1, a1[p]);
                    a2[p] = fma2(hv[p], w2, a2[p]);
                    a3[p] = fma2(hv[p], w3, a3[p]);
                }
            }
            float hn[RPS];
            #pragma unroll
            for (int p = 0; p < 4; ++p)
                lstm_act2(a0[p], a1[p], a2[p], a3[p], c1 + 2 * p, hn + 2 * p);
            float* dst = h1n + j * HP + r0;
            *(float4*)dst       = make_float4(hn[0], hn[1], hn[2], hn[3]);
            *(float4*)(dst + 4) = make_float4(hn[4], hn[5], hn[6], hn[7]);
        }
        __syncthreads();   // h1(new) visible

        // ================= Layer 2: gates + pointwise, write h2(new) =================
        {
            ull a0[4], a1[4], a2[4], a3[4];
            #pragma unroll
            for (int p = 0; p < 4; ++p) {
                a0[p] = b2d[0]; a1[p] = b2d[1]; a2[p] = b2d[2]; a3[p] = b2d[3];
            }
            #pragma unroll 3
            for (int k = 0; k < NS; ++k) {
                float4 wi = wqi2[k * WQP + j];
                float4 wh = wqh2[k * WQP + j];
                ull wi0 = pack2(wi.x, wi.x), wi1d = pack2(wi.y, wi.y);
                ull wi2d = pack2(wi.z, wi.z), wi3 = pack2(wi.w, wi.w);
                ull wh0 = pack2(wh.x, wh.x), wh1d = pack2(wh.y, wh.y);
                ull wh2d = pack2(wh.z, wh.z), wh3 = pack2(wh.w, wh.w);
                const float* p1 = h1n + k * HP + r0;
                const float* p2 = h2o + k * HP + r0;
                ulonglong2 h1A = *(const ulonglong2*)p1;
                ulonglong2 h1B = *(const ulonglong2*)(p1 + 4);
                ulonglong2 h2A = *(const ulonglong2*)p2;
                ulonglong2 h2B = *(const ulonglong2*)(p2 + 4);
                ull hv1[4] = {h1A.x, h1A.y, h1B.x, h1B.y};
                ull hv2[4] = {h2A.x, h2A.y, h2B.x, h2B.y};
                #pragma unroll
                for (int p = 0; p < 4; ++p) {
                    a0[p] = fma2(hv1[p], wi0,  a0[p]);
                    a1[p] = fma2(hv1[p], wi1d, a1[p]);
                    a2[p] = fma2(hv1[p], wi2d, a2[p]);
                    a3[p] = fma2(hv1[p], wi3,  a3[p]);
                    a0[p] = fma2(hv2[p], wh0,  a0[p]);
                    a1[p] = fma2(hv2[p], wh1d, a1[p]);
                    a2[p] = fma2(hv2[p], wh2d, a2[p]);
                    a3[p] = fma2(hv2[p], wh3,  a3[p]);
                }
            }
            float hn[RPS];
            #pragma unroll
            for (int p = 0; p < 4; ++p)
                lstm_act2(a0[p], a1[p], a2[p], a3[p], c2 + 2 * p, hn + 2 * p);
            float* dst = h2n + j * HP + r0;
            *(float4*)dst       = make_float4(hn[0], hn[1], hn[2], hn[3]);
            *(float4*)(dst + 4) = make_float4(hn[4], hn[5], hn[6], hn[7]);
        }
        __syncthreads();   // h2(new) visible

        // ====== output projection (threads 0..63) + next-x prefetch (64..127) ======
        if (tid < ROWS) {
            float acc = blin_v;
            #pragma unroll
            for (int k = 0; k < NS; ++k)
                acc = fmaf(h2n[k * HP + tid], wls[k], acc);
            out[(size_t)(rb + tid) * T_LEN + t] = acc;
        } else if (tid < 2 * ROWS) {
            int r = tid - ROWS;
            if (t + 1 < T_LEN)
                xs[r] = x[(size_t)(rb + r) * T_LEN + (t + 1)];
        }
        __syncthreads();   // xs ready; h-buffer roles flip
        bf = nb;
    }
}

extern "C" void kernel_launch(void* const* d_in, const int* in_sizes, int n_in,
                              void* d_out, int out_size) {
    const float* x    = (const float*)d_in[0];
    const float* Wih1 = (const float*)d_in[1];
    const float* Whh1 = (const float*)d_in[2];
    const float* bih1 = (const float*)d_in[3];
    const float* bhh1 = (const float*)d_in[4];
    const float* Wih2 = (const float*)d_in[5];
    const float* Whh2 = (const float*)d_in[6];
    const float* bih2 = (const float*)d_in[7];
    const float* bhh2 = (const float*)d_in[8];
    const float* Wlin = (const float*)d_in[9];
    const float* blin = (const float*)d_in[10];
    float* out = (float*)d_out;

    size_t smem = (size_t)(3 * NS * WQP * 4 + 4 * HSZ + 3 * NG + 52 + ROWS) * sizeof(float);
    cudaFuncSetAttribute(lstm2_f32x2_kernel,
                         cudaFuncAttributeMaxDynamicSharedMemorySize, (int)smem);

    dim3 grid(B_TOT / ROWS);      // 128 blocks
    dim3 block(NTHREADS);         // 408 threads
    lstm2_f32x2_kernel<<<grid, block, smem>>>(
        x, Wih1, Whh1, bih1, bhh1, Wih2, Whh2, bih2, bhh2, Wlin, blin, out);
}